// round 9
// baseline (speedup 1.0000x reference)
#include <cuda_runtime.h>
#include <cstdint>

#define BB 8
#define CC 192
#define HH 128
#define WW 256
#define HWSZ (HH*WW)

#define HT 4
#define WT 64
#define NC 8                      // channels per stage
#define NSTAGE (CC/NC)            // 24
#define THREADS 384               // 12 warps, 3 per SMSP

#define X1_WORDS (HT*WT)          // 256
#define X2_ROWS (HT+8)            // 12
#define X2_COLS (WT+8)            // 72
#define X2_WORDS (X2_ROWS*X2_COLS)// 864
#define CH_WORDS (X1_WORDS + X2_WORDS)   // 1120
#define VECS_PER_CH (CH_WORDS/4)  // 280
#define X1_VECS (X1_WORDS/4)      // 64
#define TOT_VECS (NC*VECS_PER_CH) // 2240
#define STAGE_WORDS (NC*CH_WORDS) // 8960
#define NSLOT 6                   // ceil(2240/384)
#define SMEM_BYTES (2*STAGE_WORDS*4)   // 71680

// 16B-slot XOR swizzle (conflict-free LDS.128 for the 8-float pixel stride).
__device__ __forceinline__ int swz(int s) { return s ^ ((s >> 3) & 4); }

__device__ __forceinline__ uint32_t smem_u32(const void* p) {
    return (uint32_t)__cvta_generic_to_shared(p);
}
__device__ __forceinline__ void cp_async16(uint32_t dst, const float* src, int srcsize) {
    asm volatile("cp.async.cg.shared.global [%0], [%1], 16, %2;\n"
                 :: "r"(dst), "l"(src), "r"(srcsize));
}
__device__ __forceinline__ void cp_commit() {
    asm volatile("cp.async.commit_group;\n" ::: "memory");
}
__device__ __forceinline__ void cp_wait_all() {
    asm volatile("cp.async.wait_group 0;\n" ::: "memory");
}

// One stage (NC channels) for a warp owning pairs [P0, P0+CNT).
// pair = 9*ir + j  (ir = di+4, j = dj+4). Consecutive pairs span <= 2 i-rows.
// vA = x2 halo row for IRA, vB = row for IRA+1 (loaded only if needed).
template<int P0, int CNT>
__device__ __forceinline__ void do_stage(const float* __restrict__ sbuf,
    int sw1a, int sw1b,
    int swA0, int swA1, int swA2, int swA3,
    int swB0, int swB1, int swB2, int swB3,
    float (&acc)[7][8]) {
    constexpr int IRA = P0 / 9;
    constexpr int IRB = (P0 + CNT - 1) / 9;
    constexpr bool TWO = (IRB != IRA);
    #pragma unroll 2
    for (int ch = 0; ch < NC; ++ch) {
        const float* p1 = sbuf + ch*CH_WORDS;
        const float* p2 = p1 + X1_WORDS;

        float a[8];
        *(float4*)(a)   = *(const float4*)(p1 + sw1a);
        *(float4*)(a+4) = *(const float4*)(p1 + sw1b);

        float vA[16];
        *(float4*)(vA)    = *(const float4*)(p2 + swA0);
        *(float4*)(vA+4)  = *(const float4*)(p2 + swA1);
        *(float4*)(vA+8)  = *(const float4*)(p2 + swA2);
        *(float4*)(vA+12) = *(const float4*)(p2 + swA3);

        float vB[16];
        if (TWO) {
            *(float4*)(vB)    = *(const float4*)(p2 + swB0);
            *(float4*)(vB+4)  = *(const float4*)(p2 + swB1);
            *(float4*)(vB+8)  = *(const float4*)(p2 + swB2);
            *(float4*)(vB+12) = *(const float4*)(p2 + swB3);
        }

        #pragma unroll
        for (int k = 0; k < CNT; ++k) {
            const int pair = P0 + k;
            const int ir   = pair / 9;      // folds to constant per unrolled k
            const int j    = pair - ir*9;
            const float* v = (ir == IRA) ? vA : vB;
            #pragma unroll
            for (int p = 0; p < 8; ++p)
                acc[k][p] = fmaf(a[p], v[p + 8 - j], acc[k][p]);
        }
    }
}

__global__ __launch_bounds__(THREADS, 1)
void costvol_kernel(const float* __restrict__ x1,
                    const float* __restrict__ x2,
                    float* __restrict__ out) {
    extern __shared__ __align__(16) float smem[];   // [2][STAGE_WORDS]

    const int tid  = threadIdx.x;
    const int wid  = tid >> 5;        // 0..11
    const int lane = tid & 31;
    const int hl   = lane >> 3;       // h row in tile
    const int g    = lane & 7;        // 8-px group

    const int b  = blockIdx.z;
    const int h0 = blockIdx.y * HT;
    const int w0 = blockIdx.x * WT;

    // pair range for this warp: warps 0..8 -> 7 pairs, warps 9..11 -> 6
    const int start = (wid < 9) ? 7*wid : 63 + 6*(wid - 9);
    const int cnt   = (wid < 9) ? 7 : 6;
    const int irA   = start / 9;      // first i-row this warp touches

    // ---- staging tasks (fixed per thread; only channel advances) ----
    const float* tsrc[NSLOT];
    int tof[NSLOT];
    int tsz[NSLOT];
    #pragma unroll
    for (int k = 0; k < NSLOT; ++k) {
        int t = tid + k * THREADS;
        if (t < TOT_VECS) {
            int ch = t / VECS_PER_CH;
            int r  = t - ch * VECS_PER_CH;
            if (r < X1_VECS) {
                int hr = r >> 4;
                int v  = r & 15;
                tsrc[k] = x1 + ((b*CC + ch)*HWSZ) + (h0 + hr)*WW + w0 + 4*v;
                tof[k]  = ch*CH_WORDS + swz(hr*WT + 4*v);
                tsz[k]  = 16;
            } else {
                int r2  = r - X1_VECS;
                int row = r2 / 18;
                int v   = r2 - row*18;
                int gh  = h0 - 4 + row;
                int gw  = w0 - 4 + 4*v;
                int ok  = (gh >= 0) && (gh < HH) && (gw >= 0) && (gw <= WW-4);
                int ghc = min(max(gh, 0), HH-1);
                int gwc = min(max(gw, 0), WW-4);
                tsrc[k] = x2 + ((b*CC + ch)*HWSZ) + ghc*WW + gwc;
                tof[k]  = ch*CH_WORDS + X1_WORDS + swz(row*X2_COLS + 4*v);
                tsz[k]  = ok ? 16 : 0;
            }
        } else {
            tsrc[k] = x1;
            tof[k]  = 0;
            tsz[k]  = -1;
        }
    }

    const uint32_t sb0 = smem_u32(&smem[0]);
    const uint32_t sb1 = smem_u32(&smem[STAGE_WORDS]);

    // ---- compute offsets (swizzled, hoisted) ----
    // halo row for i-row ir at tile row hl: rr = hl + 8 - ir
    const int s1b  = hl*WT + 8*g;
    const int sw1a = swz(s1b), sw1b = swz(s1b + 4);
    const int s2A  = (hl + 8 - irA)*X2_COLS + 8*g;   // row irA
    const int s2B  = s2A - X2_COLS;                   // row irA+1
    const int swA0 = swz(s2A),     swA1 = swz(s2A + 4);
    const int swA2 = swz(s2A + 8), swA3 = swz(s2A + 12);
    const int swB0 = swz(s2B),     swB1 = swz(s2B + 4);
    const int swB2 = swz(s2B + 8), swB3 = swz(s2B + 12);

    float acc[7][8];
    #pragma unroll
    for (int k = 0; k < 7; ++k)
        #pragma unroll
        for (int p = 0; p < 8; ++p) acc[k][p] = 0.0f;

    // ---- prologue ----
    #pragma unroll
    for (int k = 0; k < NSLOT; ++k)
        if (tsz[k] >= 0) cp_async16(sb0 + (uint32_t)tof[k]*4u, tsrc[k], tsz[k]);
    cp_commit();
    cp_wait_all();
    __syncthreads();

    // ---- main loop: prefetch s+1 while computing s ----
    for (int s = 0; s < NSTAGE; ++s) {
        const int buf = s & 1;
        if (s + 1 < NSTAGE) {
            const uint32_t sbn = (buf ? sb0 : sb1);
            const int adv = (s + 1) * NC * HWSZ;
            #pragma unroll
            for (int k = 0; k < NSLOT; ++k)
                if (tsz[k] >= 0) cp_async16(sbn + (uint32_t)tof[k]*4u, tsrc[k] + adv, tsz[k]);
            cp_commit();
        }

        const float* sbuf = smem + buf*STAGE_WORDS;
        switch (wid) {
          case 0:  do_stage<0,7>(sbuf, sw1a, sw1b, swA0,swA1,swA2,swA3, swB0,swB1,swB2,swB3, acc); break;
          case 1:  do_stage<7,7>(sbuf, sw1a, sw1b, swA0,swA1,swA2,swA3, swB0,swB1,swB2,swB3, acc); break;
          case 2:  do_stage<14,7>(sbuf, sw1a, sw1b, swA0,swA1,swA2,swA3, swB0,swB1,swB2,swB3, acc); break;
          case 3:  do_stage<21,7>(sbuf, sw1a, sw1b, swA0,swA1,swA2,swA3, swB0,swB1,swB2,swB3, acc); break;
          case 4:  do_stage<28,7>(sbuf, sw1a, sw1b, swA0,swA1,swA2,swA3, swB0,swB1,swB2,swB3, acc); break;
          case 5:  do_stage<35,7>(sbuf, sw1a, sw1b, swA0,swA1,swA2,swA3, swB0,swB1,swB2,swB3, acc); break;
          case 6:  do_stage<42,7>(sbuf, sw1a, sw1b, swA0,swA1,swA2,swA3, swB0,swB1,swB2,swB3, acc); break;
          case 7:  do_stage<49,7>(sbuf, sw1a, sw1b, swA0,swA1,swA2,swA3, swB0,swB1,swB2,swB3, acc); break;
          case 8:  do_stage<56,7>(sbuf, sw1a, sw1b, swA0,swA1,swA2,swA3, swB0,swB1,swB2,swB3, acc); break;
          case 9:  do_stage<63,6>(sbuf, sw1a, sw1b, swA0,swA1,swA2,swA3, swB0,swB1,swB2,swB3, acc); break;
          case 10: do_stage<69,6>(sbuf, sw1a, sw1b, swA0,swA1,swA2,swA3, swB0,swB1,swB2,swB3, acc); break;
          default: do_stage<75,6>(sbuf, sw1a, sw1b, swA0,swA1,swA2,swA3, swB0,swB1,swB2,swB3, acc); break;
        }

        cp_wait_all();
        __syncthreads();
    }

    // ---- epilogue ----
    const float inv = 1.0f / 81.0f;
    const int h = h0 + hl;
    float* obase = out + (b*81)*HWSZ + h*WW + w0 + 8*g;
    for (int k = 0; k < cnt; ++k) {
        int pair = start + k;
        int idx = pair + 41;            // (pair - 40) mod 81
        if (idx >= 81) idx -= 81;
        float* op = obase + idx*HWSZ;
        *(float4*)(op)   = make_float4(acc[k][0]*inv, acc[k][1]*inv,
                                       acc[k][2]*inv, acc[k][3]*inv);
        *(float4*)(op+4) = make_float4(acc[k][4]*inv, acc[k][5]*inv,
                                       acc[k][6]*inv, acc[k][7]*inv);
    }
}

extern "C" void kernel_launch(void* const* d_in, const int* in_sizes, int n_in,
                              void* d_out, int out_size) {
    const float* x1 = (const float*)d_in[0];
    const float* x2 = (const float*)d_in[1];
    float* out = (float*)d_out;
    cudaFuncSetAttribute(costvol_kernel,
                         cudaFuncAttributeMaxDynamicSharedMemorySize, SMEM_BYTES);
    dim3 grid(WW/WT, HH/HT, BB);   // (4, 32, 8)
    dim3 block(THREADS);
    costvol_kernel<<<grid, block, SMEM_BYTES>>>(x1, x2, out);
}

// round 10
// speedup vs baseline: 1.6501x; 1.6501x over previous
#include <cuda_runtime.h>
#include <cstdint>

#define BB 8
#define CC 192
#define HH 128
#define WW 256
#define HWSZ (HH*WW)

#define HT 4
#define WT 64
#define NC 8                      // channels per stage
#define NSTAGE (CC/NC)            // 24
#define THREADS 384               // 12 warps, 3 per SMSP

#define X1_WORDS (HT*WT)          // 256
#define X2_ROWS (HT+8)            // 12
#define X2_COLS (WT+8)            // 72
#define X2_WORDS (X2_ROWS*X2_COLS)// 864
#define CH_WORDS (X1_WORDS + X2_WORDS)   // 1120
#define VECS_PER_CH (CH_WORDS/4)  // 280
#define X1_VECS (X1_WORDS/4)      // 64
#define TOT_VECS (NC*VECS_PER_CH) // 2240
#define STAGE_WORDS (NC*CH_WORDS) // 8960
#define NSLOT 6                   // ceil(2240/384)
#define SMEM_BYTES (2*STAGE_WORDS*4)   // 71680

// 16B-slot XOR swizzle (conflict-free LDS.128 for the 8-float pixel stride).
__device__ __forceinline__ int swz(int s) { return s ^ ((s >> 3) & 4); }

__device__ __forceinline__ uint32_t smem_u32(const void* p) {
    return (uint32_t)__cvta_generic_to_shared(p);
}
__device__ __forceinline__ void cp_async16(uint32_t dst, const float* src, int srcsize) {
    asm volatile("cp.async.cg.shared.global [%0], [%1], 16, %2;\n"
                 :: "r"(dst), "l"(src), "r"(srcsize));
}
__device__ __forceinline__ void cp_commit() {
    asm volatile("cp.async.commit_group;\n" ::: "memory");
}
__device__ __forceinline__ void cp_wait_all() {
    asm volatile("cp.async.wait_group 0;\n" ::: "memory");
}

// One stage (NC channels) for a warp owning pairs [P0, P0+CNT).
// pair = 9*ir + j  (ir = di+4, j = dj+4). Consecutive pairs span <= 2 i-rows.
template<int P0, int CNT>
__device__ __forceinline__ void do_stage(const float* __restrict__ sbuf,
    int sw1a, int sw1b,
    int swA0, int swA1, int swA2, int swA3,
    int swB0, int swB1, int swB2, int swB3,
    float (&acc)[7][8]) {
    constexpr int IRA = P0 / 9;
    constexpr int IRB = (P0 + CNT - 1) / 9;
    constexpr bool TWO = (IRB != IRA);
    #pragma unroll 2
    for (int ch = 0; ch < NC; ++ch) {
        const float* p1 = sbuf + ch*CH_WORDS;
        const float* p2 = p1 + X1_WORDS;

        float a[8];
        *(float4*)(a)   = *(const float4*)(p1 + sw1a);
        *(float4*)(a+4) = *(const float4*)(p1 + sw1b);

        float vA[16];
        *(float4*)(vA)    = *(const float4*)(p2 + swA0);
        *(float4*)(vA+4)  = *(const float4*)(p2 + swA1);
        *(float4*)(vA+8)  = *(const float4*)(p2 + swA2);
        *(float4*)(vA+12) = *(const float4*)(p2 + swA3);

        float vB[16];
        if (TWO) {
            *(float4*)(vB)    = *(const float4*)(p2 + swB0);
            *(float4*)(vB+4)  = *(const float4*)(p2 + swB1);
            *(float4*)(vB+8)  = *(const float4*)(p2 + swB2);
            *(float4*)(vB+12) = *(const float4*)(p2 + swB3);
        }

        #pragma unroll
        for (int k = 0; k < CNT; ++k) {
            constexpr_hint:;
            const int pair = P0 + k;
            const int ir   = pair / 9;       // constant per unrolled k
            const int j    = pair - ir*9;
            const float* v = (ir == IRA) ? vA : vB;
            #pragma unroll
            for (int p = 0; p < 8; ++p)
                acc[k][p] = fmaf(a[p], v[p + 8 - j], acc[k][p]);
        }
    }
}

__global__ __launch_bounds__(THREADS, 1)
void costvol_kernel(const float* __restrict__ x1,
                    const float* __restrict__ x2,
                    float* __restrict__ out) {
    extern __shared__ __align__(16) float smem[];   // [2][STAGE_WORDS]

    const int tid  = threadIdx.x;
    const int wid  = tid >> 5;        // 0..11
    const int lane = tid & 31;
    const int hl   = lane >> 3;       // h row in tile
    const int g    = lane & 7;        // 8-px group

    const int b  = blockIdx.z;
    const int h0 = blockIdx.y * HT;
    const int w0 = blockIdx.x * WT;

    // pair range: warps 0..8 -> 7 pairs, warps 9..11 -> 6
    const int start = (wid < 9) ? 7*wid : 63 + 6*(wid - 9);
    const int cnt   = (wid < 9) ? 7 : 6;
    const int irA   = start / 9;

    // ---- staging tasks ----
    const float* tsrc[NSLOT];
    int tof[NSLOT];
    int tsz[NSLOT];
    #pragma unroll
    for (int k = 0; k < NSLOT; ++k) {
        int t = tid + k * THREADS;
        if (t < TOT_VECS) {
            int ch = t / VECS_PER_CH;
            int r  = t - ch * VECS_PER_CH;
            if (r < X1_VECS) {
                int hr = r >> 4;
                int v  = r & 15;
                tsrc[k] = x1 + ((b*CC + ch)*HWSZ) + (h0 + hr)*WW + w0 + 4*v;
                tof[k]  = ch*CH_WORDS + swz(hr*WT + 4*v);
                tsz[k]  = 16;
            } else {
                int r2  = r - X1_VECS;
                int row = r2 / 18;
                int v   = r2 - row*18;
                int gh  = h0 - 4 + row;
                int gw  = w0 - 4 + 4*v;
                int ok  = (gh >= 0) && (gh < HH) && (gw >= 0) && (gw <= WW-4);
                int ghc = min(max(gh, 0), HH-1);
                int gwc = min(max(gw, 0), WW-4);
                tsrc[k] = x2 + ((b*CC + ch)*HWSZ) + ghc*WW + gwc;
                tof[k]  = ch*CH_WORDS + X1_WORDS + swz(row*X2_COLS + 4*v);
                tsz[k]  = ok ? 16 : 0;
            }
        } else {
            tsrc[k] = x1;
            tof[k]  = 0;
            tsz[k]  = -1;
        }
    }

    const uint32_t sb0 = smem_u32(&smem[0]);
    const uint32_t sb1 = smem_u32(&smem[STAGE_WORDS]);

    // ---- compute offsets (swizzled, hoisted) ----
    const int s1b  = hl*WT + 8*g;
    const int sw1a = swz(s1b), sw1b = swz(s1b + 4);
    const int s2A  = (hl + 8 - irA)*X2_COLS + 8*g;   // halo row for irA
    const int s2B  = s2A - X2_COLS;                   // row irA+1
    const int swA0 = swz(s2A),     swA1 = swz(s2A + 4);
    const int swA2 = swz(s2A + 8), swA3 = swz(s2A + 12);
    const int swB0 = swz(s2B),     swB1 = swz(s2B + 4);
    const int swB2 = swz(s2B + 8), swB3 = swz(s2B + 12);

    float acc[7][8];
    #pragma unroll
    for (int k = 0; k < 7; ++k)
        #pragma unroll
        for (int p = 0; p < 8; ++p) acc[k][p] = 0.0f;

    // ---- prologue ----
    #pragma unroll
    for (int k = 0; k < NSLOT; ++k)
        if (tsz[k] >= 0) cp_async16(sb0 + (uint32_t)tof[k]*4u, tsrc[k], tsz[k]);
    cp_commit();
    cp_wait_all();
    __syncthreads();

    // ---- main loop ----
    for (int s = 0; s < NSTAGE; ++s) {
        const int buf = s & 1;
        if (s + 1 < NSTAGE) {
            const uint32_t sbn = (buf ? sb0 : sb1);
            const int adv = (s + 1) * NC * HWSZ;
            #pragma unroll
            for (int k = 0; k < NSLOT; ++k)
                if (tsz[k] >= 0) cp_async16(sbn + (uint32_t)tof[k]*4u, tsrc[k] + adv, tsz[k]);
            cp_commit();
        }

        const float* sbuf = smem + buf*STAGE_WORDS;
        switch (wid) {
          case 0:  do_stage<0,7>(sbuf, sw1a, sw1b, swA0,swA1,swA2,swA3, swB0,swB1,swB2,swB3, acc); break;
          case 1:  do_stage<7,7>(sbuf, sw1a, sw1b, swA0,swA1,swA2,swA3, swB0,swB1,swB2,swB3, acc); break;
          case 2:  do_stage<14,7>(sbuf, sw1a, sw1b, swA0,swA1,swA2,swA3, swB0,swB1,swB2,swB3, acc); break;
          case 3:  do_stage<21,7>(sbuf, sw1a, sw1b, swA0,swA1,swA2,swA3, swB0,swB1,swB2,swB3, acc); break;
          case 4:  do_stage<28,7>(sbuf, sw1a, sw1b, swA0,swA1,swA2,swA3, swB0,swB1,swB2,swB3, acc); break;
          case 5:  do_stage<35,7>(sbuf, sw1a, sw1b, swA0,swA1,swA2,swA3, swB0,swB1,swB2,swB3, acc); break;
          case 6:  do_stage<42,7>(sbuf, sw1a, sw1b, swA0,swA1,swA2,swA3, swB0,swB1,swB2,swB3, acc); break;
          case 7:  do_stage<49,7>(sbuf, sw1a, sw1b, swA0,swA1,swA2,swA3, swB0,swB1,swB2,swB3, acc); break;
          case 8:  do_stage<56,7>(sbuf, sw1a, sw1b, swA0,swA1,swA2,swA3, swB0,swB1,swB2,swB3, acc); break;
          case 9:  do_stage<63,6>(sbuf, sw1a, sw1b, swA0,swA1,swA2,swA3, swB0,swB1,swB2,swB3, acc); break;
          case 10: do_stage<69,6>(sbuf, sw1a, sw1b, swA0,swA1,swA2,swA3, swB0,swB1,swB2,swB3, acc); break;
          default: do_stage<75,6>(sbuf, sw1a, sw1b, swA0,swA1,swA2,swA3, swB0,swB1,swB2,swB3, acc); break;
        }

        cp_wait_all();
        __syncthreads();
    }

    // ---- epilogue: compile-time bounds so acc stays in registers ----
    const float inv = 1.0f / 81.0f;
    const int h = h0 + hl;
    float* obase = out + (b*81)*HWSZ + h*WW + w0 + 8*g;
    #pragma unroll
    for (int k = 0; k < 7; ++k) {
        if (k < cnt) {
            int pair = start + k;
            int idx = pair + 41;            // (pair - 40) mod 81
            if (idx >= 81) idx -= 81;
            float* op = obase + idx*HWSZ;
            *(float4*)(op)   = make_float4(acc[k][0]*inv, acc[k][1]*inv,
                                           acc[k][2]*inv, acc[k][3]*inv);
            *(float4*)(op+4) = make_float4(acc[k][4]*inv, acc[k][5]*inv,
                                           acc[k][6]*inv, acc[k][7]*inv);
        }
    }
}

extern "C" void kernel_launch(void* const* d_in, const int* in_sizes, int n_in,
                              void* d_out, int out_size) {
    const float* x1 = (const float*)d_in[0];
    const float* x2 = (const float*)d_in[1];
    float* out = (float*)d_out;
    cudaFuncSetAttribute(costvol_kernel,
                         cudaFuncAttributeMaxDynamicSharedMemorySize, SMEM_BYTES);
    dim3 grid(WW/WT, HH/HT, BB);   // (4, 32, 8)
    dim3 block(THREADS);
    costvol_kernel<<<grid, block, SMEM_BYTES>>>(x1, x2, out);
}

// round 11
// speedup vs baseline: 1.6539x; 1.0023x over previous
#include <cuda_runtime.h>
#include <cstdint>

#define BB 8
#define CC 192
#define HH 128
#define WW 256
#define HWSZ (HH*WW)

#define HT 4
#define WT 64
#define NC 8                      // channels per stage
#define NSTAGE (CC/NC)            // 24
#define THREADS 384               // 12 warps, 3 per SMSP

#define X1_WORDS (HT*WT)          // 256
#define X2_ROWS (HT+8)            // 12
#define X2_COLS (WT+8)            // 72
#define X2_WORDS (X2_ROWS*X2_COLS)// 864
#define CH_WORDS (X1_WORDS + X2_WORDS)   // 1120
#define VECS_PER_CH (CH_WORDS/4)  // 280
#define X1_VECS (X1_WORDS/4)      // 64
#define TOT_VECS (NC*VECS_PER_CH) // 2240
#define STAGE_WORDS (NC*CH_WORDS) // 8960
#define NSLOT 6                   // ceil(2240/384)
#define SMEM_BYTES (2*STAGE_WORDS*4)   // 71680

// 16B-slot XOR swizzle (conflict-free LDS.128 for the 8-float pixel stride).
__device__ __forceinline__ int swz(int s) { return s ^ ((s >> 3) & 4); }

__device__ __forceinline__ uint32_t smem_u32(const void* p) {
    return (uint32_t)__cvta_generic_to_shared(p);
}
__device__ __forceinline__ void cp_async16(uint32_t dst, const float* src, int srcsize) {
    asm volatile("cp.async.cg.shared.global [%0], [%1], 16, %2;\n"
                 :: "r"(dst), "l"(src), "r"(srcsize));
}
__device__ __forceinline__ void cp_commit() {
    asm volatile("cp.async.commit_group;\n" ::: "memory");
}
__device__ __forceinline__ void cp_wait_all() {
    asm volatile("cp.async.wait_group 0;\n" ::: "memory");
}

// One stage (NC channels) for a warp owning pairs [P0, P0+CNT).
// pair = 9*ir + j. Pairs split at the compile-time row boundary so every
// v-array subscript is static (NO pointer select between local arrays —
// that demotes them to local memory; learned rounds 9/10).
template<int P0, int CNT>
__device__ __forceinline__ void do_stage(const float* __restrict__ sbuf,
    int sw1a, int sw1b,
    int swA0, int swA1, int swA2, int swA3,
    int swB0, int swB1, int swB2, int swB3,
    float (&acc)[7][8]) {
    constexpr int IRA   = P0 / 9;
    constexpr int REND  = 9*(IRA + 1);
    constexpr int SPLIT = (P0 + CNT < REND) ? CNT : (REND - P0);
    constexpr bool TWO  = (SPLIT < CNT);
    #pragma unroll 2
    for (int ch = 0; ch < NC; ++ch) {
        const float* p1 = sbuf + ch*CH_WORDS;
        const float* p2 = p1 + X1_WORDS;

        float a[8];
        *(float4*)(a)   = *(const float4*)(p1 + sw1a);
        *(float4*)(a+4) = *(const float4*)(p1 + sw1b);

        float vA[16];
        *(float4*)(vA)    = *(const float4*)(p2 + swA0);
        *(float4*)(vA+4)  = *(const float4*)(p2 + swA1);
        *(float4*)(vA+8)  = *(const float4*)(p2 + swA2);
        *(float4*)(vA+12) = *(const float4*)(p2 + swA3);

        float vB[16];
        if (TWO) {
            *(float4*)(vB)    = *(const float4*)(p2 + swB0);
            *(float4*)(vB+4)  = *(const float4*)(p2 + swB1);
            *(float4*)(vB+8)  = *(const float4*)(p2 + swB2);
            *(float4*)(vB+12) = *(const float4*)(p2 + swB3);
        }

        // pairs in row IRA — static vA indices
        #pragma unroll
        for (int k = 0; k < SPLIT; ++k) {
            const int j = (P0 + k) - 9*IRA;
            #pragma unroll
            for (int p = 0; p < 8; ++p)
                acc[k][p] = fmaf(a[p], vA[p + 8 - j], acc[k][p]);
        }
        // pairs in row IRA+1 — static vB indices
        if (TWO) {
            #pragma unroll
            for (int k = SPLIT; k < CNT; ++k) {
                const int j = (P0 + k) - REND;
                #pragma unroll
                for (int p = 0; p < 8; ++p)
                    acc[k][p] = fmaf(a[p], vB[p + 8 - j], acc[k][p]);
            }
        }
    }
}

__global__ __launch_bounds__(THREADS, 1)
void costvol_kernel(const float* __restrict__ x1,
                    const float* __restrict__ x2,
                    float* __restrict__ out) {
    extern __shared__ __align__(16) float smem[];   // [2][STAGE_WORDS]

    const int tid  = threadIdx.x;
    const int wid  = tid >> 5;        // 0..11
    const int lane = tid & 31;
    const int hl   = lane >> 3;       // h row in tile
    const int g    = lane & 7;        // 8-px group

    const int b  = blockIdx.z;
    const int h0 = blockIdx.y * HT;
    const int w0 = blockIdx.x * WT;

    // pair range: warps 0..8 -> 7 pairs, warps 9..11 -> 6
    const int start = (wid < 9) ? 7*wid : 63 + 6*(wid - 9);
    const int cnt   = (wid < 9) ? 7 : 6;
    const int irA   = start / 9;

    // ---- staging tasks ----
    const float* tsrc[NSLOT];
    int tof[NSLOT];
    int tsz[NSLOT];
    #pragma unroll
    for (int k = 0; k < NSLOT; ++k) {
        int t = tid + k * THREADS;
        if (t < TOT_VECS) {
            int ch = t / VECS_PER_CH;
            int r  = t - ch * VECS_PER_CH;
            if (r < X1_VECS) {
                int hr = r >> 4;
                int v  = r & 15;
                tsrc[k] = x1 + ((b*CC + ch)*HWSZ) + (h0 + hr)*WW + w0 + 4*v;
                tof[k]  = ch*CH_WORDS + swz(hr*WT + 4*v);
                tsz[k]  = 16;
            } else {
                int r2  = r - X1_VECS;
                int row = r2 / 18;
                int v   = r2 - row*18;
                int gh  = h0 - 4 + row;
                int gw  = w0 - 4 + 4*v;
                int ok  = (gh >= 0) && (gh < HH) && (gw >= 0) && (gw <= WW-4);
                int ghc = min(max(gh, 0), HH-1);
                int gwc = min(max(gw, 0), WW-4);
                tsrc[k] = x2 + ((b*CC + ch)*HWSZ) + ghc*WW + gwc;
                tof[k]  = ch*CH_WORDS + X1_WORDS + swz(row*X2_COLS + 4*v);
                tsz[k]  = ok ? 16 : 0;
            }
        } else {
            tsrc[k] = x1;
            tof[k]  = 0;
            tsz[k]  = -1;
        }
    }

    const uint32_t sb0 = smem_u32(&smem[0]);
    const uint32_t sb1 = smem_u32(&smem[STAGE_WORDS]);

    // ---- compute offsets (swizzled, hoisted) ----
    const int s1b  = hl*WT + 8*g;
    const int sw1a = swz(s1b), sw1b = swz(s1b + 4);
    const int s2A  = (hl + 8 - irA)*X2_COLS + 8*g;   // halo row for irA
    const int s2B  = s2A - X2_COLS;                   // row irA+1
    const int swA0 = swz(s2A),     swA1 = swz(s2A + 4);
    const int swA2 = swz(s2A + 8), swA3 = swz(s2A + 12);
    const int swB0 = swz(s2B),     swB1 = swz(s2B + 4);
    const int swB2 = swz(s2B + 8), swB3 = swz(s2B + 12);

    float acc[7][8];
    #pragma unroll
    for (int k = 0; k < 7; ++k)
        #pragma unroll
        for (int p = 0; p < 8; ++p) acc[k][p] = 0.0f;

    // ---- prologue ----
    #pragma unroll
    for (int k = 0; k < NSLOT; ++k)
        if (tsz[k] >= 0) cp_async16(sb0 + (uint32_t)tof[k]*4u, tsrc[k], tsz[k]);
    cp_commit();
    cp_wait_all();
    __syncthreads();

    // ---- main loop ----
    for (int s = 0; s < NSTAGE; ++s) {
        const int buf = s & 1;
        if (s + 1 < NSTAGE) {
            const uint32_t sbn = (buf ? sb0 : sb1);
            const int adv = (s + 1) * NC * HWSZ;
            #pragma unroll
            for (int k = 0; k < NSLOT; ++k)
                if (tsz[k] >= 0) cp_async16(sbn + (uint32_t)tof[k]*4u, tsrc[k] + adv, tsz[k]);
            cp_commit();
        }

        const float* sbuf = smem + buf*STAGE_WORDS;
        switch (wid) {
          case 0:  do_stage<0,7>(sbuf, sw1a, sw1b, swA0,swA1,swA2,swA3, swB0,swB1,swB2,swB3, acc); break;
          case 1:  do_stage<7,7>(sbuf, sw1a, sw1b, swA0,swA1,swA2,swA3, swB0,swB1,swB2,swB3, acc); break;
          case 2:  do_stage<14,7>(sbuf, sw1a, sw1b, swA0,swA1,swA2,swA3, swB0,swB1,swB2,swB3, acc); break;
          case 3:  do_stage<21,7>(sbuf, sw1a, sw1b, swA0,swA1,swA2,swA3, swB0,swB1,swB2,swB3, acc); break;
          case 4:  do_stage<28,7>(sbuf, sw1a, sw1b, swA0,swA1,swA2,swA3, swB0,swB1,swB2,swB3, acc); break;
          case 5:  do_stage<35,7>(sbuf, sw1a, sw1b, swA0,swA1,swA2,swA3, swB0,swB1,swB2,swB3, acc); break;
          case 6:  do_stage<42,7>(sbuf, sw1a, sw1b, swA0,swA1,swA2,swA3, swB0,swB1,swB2,swB3, acc); break;
          case 7:  do_stage<49,7>(sbuf, sw1a, sw1b, swA0,swA1,swA2,swA3, swB0,swB1,swB2,swB3, acc); break;
          case 8:  do_stage<56,7>(sbuf, sw1a, sw1b, swA0,swA1,swA2,swA3, swB0,swB1,swB2,swB3, acc); break;
          case 9:  do_stage<63,6>(sbuf, sw1a, sw1b, swA0,swA1,swA2,swA3, swB0,swB1,swB2,swB3, acc); break;
          case 10: do_stage<69,6>(sbuf, sw1a, sw1b, swA0,swA1,swA2,swA3, swB0,swB1,swB2,swB3, acc); break;
          default: do_stage<75,6>(sbuf, sw1a, sw1b, swA0,swA1,swA2,swA3, swB0,swB1,swB2,swB3, acc); break;
        }

        cp_wait_all();
        __syncthreads();
    }

    // ---- epilogue: compile-time bounds so acc stays in registers ----
    const float inv = 1.0f / 81.0f;
    const int h = h0 + hl;
    float* obase = out + (b*81)*HWSZ + h*WW + w0 + 8*g;
    #pragma unroll
    for (int k = 0; k < 7; ++k) {
        if (k < cnt) {
            int pair = start + k;
            int idx = pair + 41;            // (pair - 40) mod 81
            if (idx >= 81) idx -= 81;
            float* op = obase + idx*HWSZ;
            *(float4*)(op)   = make_float4(acc[k][0]*inv, acc[k][1]*inv,
                                           acc[k][2]*inv, acc[k][3]*inv);
            *(float4*)(op+4) = make_float4(acc[k][4]*inv, acc[k][5]*inv,
                                           acc[k][6]*inv, acc[k][7]*inv);
        }
    }
}

extern "C" void kernel_launch(void* const* d_in, const int* in_sizes, int n_in,
                              void* d_out, int out_size) {
    const float* x1 = (const float*)d_in[0];
    const float* x2 = (const float*)d_in[1];
    float* out = (float*)d_out;
    cudaFuncSetAttribute(costvol_kernel,
                         cudaFuncAttributeMaxDynamicSharedMemorySize, SMEM_BYTES);
    dim3 grid(WW/WT, HH/HT, BB);   // (4, 32, 8)
    dim3 block(THREADS);
    costvol_kernel<<<grid, block, SMEM_BYTES>>>(x1, x2, out);
}

// round 12
// speedup vs baseline: 3.2967x; 1.9933x over previous
#include <cuda_runtime.h>
#include <cstdint>

#define BB 8
#define CC 192
#define HH 128
#define WW 256
#define HWSZ (HH*WW)

#define HT 4
#define WT 64
#define NC 8                      // channels per stage
#define NSTAGE (CC/NC)            // 24
#define THREADS 256               // 8 warps, exact SMSP balance

#define X1_WORDS (HT*WT)          // 256
#define X2_ROWS (HT+8)            // 12
#define X2_COLS (WT+8)            // 72
#define X2_WORDS (X2_ROWS*X2_COLS)// 864
#define CH_WORDS (X1_WORDS + X2_WORDS)   // 1120
#define VECS_PER_CH (CH_WORDS/4)  // 280
#define X1_VECS (X1_WORDS/4)      // 64
#define TOT_VECS (NC*VECS_PER_CH) // 2240
#define STAGE_WORDS (NC*CH_WORDS) // 8960
#define NSLOT 9                   // ceil(2240/256)
#define SMEM_BYTES (2*STAGE_WORDS*4)   // 71680

// 16B-slot XOR swizzle (conflict-free LDS.128 for the 8-float pixel stride).
__device__ __forceinline__ int swz(int s) { return s ^ ((s >> 3) & 4); }

__device__ __forceinline__ uint32_t smem_u32(const void* p) {
    return (uint32_t)__cvta_generic_to_shared(p);
}
__device__ __forceinline__ void cp_async16(uint32_t dst, const float* src, int srcsize) {
    asm volatile("cp.async.cg.shared.global [%0], [%1], 16, %2;\n"
                 :: "r"(dst), "l"(src), "r"(srcsize));
}
__device__ __forceinline__ void cp_commit() {
    asm volatile("cp.async.commit_group;\n" ::: "memory");
}
__device__ __forceinline__ void cp_wait_all() {
    asm volatile("cp.async.wait_group 0;\n" ::: "memory");
}

// Register buffer for one channel's operands.
struct ChBuf {
    float a[8];     // x1, 8 px
    float v[16];    // x2 window for main i-row
    float a8[2];    // x1, slice
    float v8[6];    // x2 window, slice
};

__device__ __forceinline__ void load_ch(ChBuf& b, const float* __restrict__ p1,
    int sw1a, int sw1b,
    int sw2a, int sw2b, int sw2c, int sw2d,
    int sw3, int sw4a, int sw4b, int sw4c) {
    const float* p2 = p1 + X1_WORDS;
    *(float4*)(b.a)    = *(const float4*)(p1 + sw1a);
    *(float4*)(b.a+4)  = *(const float4*)(p1 + sw1b);
    *(float4*)(b.v)    = *(const float4*)(p2 + sw2a);
    *(float4*)(b.v+4)  = *(const float4*)(p2 + sw2b);
    *(float4*)(b.v+8)  = *(const float4*)(p2 + sw2c);
    *(float4*)(b.v+12) = *(const float4*)(p2 + sw2d);
    *(float2*)(b.a8)   = *(const float2*)(p1 + sw3);
    *(float2*)(b.v8)   = *(const float2*)(p2 + sw4a);
    *(float2*)(b.v8+2) = *(const float2*)(p2 + sw4b);
    *(float2*)(b.v8+4) = *(const float2*)(p2 + sw4c);
}

// Main row: 72 FMA. Slice (di=+4): TJ=0 -> j 0..4 (10 FMA), TJ=1 -> j 5..8 (8).
template<int TJ>
__device__ __forceinline__ void fma_ch(const ChBuf& b,
    float (&acc)[9][8], float (&acc8)[5][2]) {
    #pragma unroll
    for (int j = 0; j < 9; ++j)
        #pragma unroll
        for (int p = 0; p < 8; ++p)
            acc[j][p] = fmaf(b.a[p], b.v[p + 8 - j], acc[j][p]);
    #pragma unroll
    for (int jj = 0; jj < (TJ ? 4 : 5); ++jj)
        #pragma unroll
        for (int p = 0; p < 2; ++p)
            acc8[jj][p] = fmaf(b.a8[p], b.v8[p + (TJ ? 3 : 4) - jj], acc8[jj][p]);
}

// One stage, software-pipelined over channels (depth 2): loads for ch+1 are
// issued before the FMA block of ch so LDS latency hides under the FMA run.
template<int TJ>
__device__ __forceinline__ void do_stage(const float* __restrict__ sbuf,
    int sw1a, int sw1b,
    int sw2a, int sw2b, int sw2c, int sw2d,
    int sw3, int sw4a, int sw4b, int sw4c,
    float (&acc)[9][8], float (&acc8)[5][2]) {
    ChBuf A, B;
    load_ch(A, sbuf, sw1a, sw1b, sw2a, sw2b, sw2c, sw2d, sw3, sw4a, sw4b, sw4c);
    #pragma unroll
    for (int ch = 0; ch < NC; ch += 2) {
        if (ch + 1 < NC)
            load_ch(B, sbuf + (ch+1)*CH_WORDS,
                    sw1a, sw1b, sw2a, sw2b, sw2c, sw2d, sw3, sw4a, sw4b, sw4c);
        fma_ch<TJ>(A, acc, acc8);
        if (ch + 2 < NC)
            load_ch(A, sbuf + (ch+2)*CH_WORDS,
                    sw1a, sw1b, sw2a, sw2b, sw2c, sw2d, sw3, sw4a, sw4b, sw4c);
        if (ch + 1 < NC)
            fma_ch<TJ>(B, acc, acc8);
    }
}

__global__ __launch_bounds__(THREADS, 1)
void costvol_kernel(const float* __restrict__ x1,
                    const float* __restrict__ x2,
                    float* __restrict__ out) {
    extern __shared__ __align__(16) float smem[];   // [2][STAGE_WORDS]

    const int tid  = threadIdx.x;
    const int wid  = tid >> 5;        // 0..7 -> main i-row (di = wid-4)
    const int lane = tid & 31;
    const int hl   = lane >> 3;       // main: h row
    const int g    = lane & 7;        // main: 8-px group
    const int hl2  = wid & 3;         // slice: h row
    const int tj   = wid >> 2;        // slice: 0 -> j 0..4, 1 -> j 5..8

    const int b  = blockIdx.z;
    const int h0 = blockIdx.y * HT;
    const int w0 = blockIdx.x * WT;

    // ---- staging tasks (fixed per thread; only channel advances) ----
    const float* tsrc[NSLOT];
    int tof[NSLOT];
    int tsz[NSLOT];
    #pragma unroll
    for (int k = 0; k < NSLOT; ++k) {
        int t = tid + k * THREADS;
        if (t < TOT_VECS) {
            int ch = t / VECS_PER_CH;
            int r  = t - ch * VECS_PER_CH;
            if (r < X1_VECS) {
                int hr = r >> 4;
                int v  = r & 15;
                tsrc[k] = x1 + ((b*CC + ch)*HWSZ) + (h0 + hr)*WW + w0 + 4*v;
                tof[k]  = ch*CH_WORDS + swz(hr*WT + 4*v);
                tsz[k]  = 16;
            } else {
                int r2  = r - X1_VECS;
                int row = r2 / 18;
                int v   = r2 - row*18;
                int gh  = h0 - 4 + row;
                int gw  = w0 - 4 + 4*v;
                int ok  = (gh >= 0) && (gh < HH) && (gw >= 0) && (gw <= WW-4);
                int ghc = min(max(gh, 0), HH-1);
                int gwc = min(max(gw, 0), WW-4);
                tsrc[k] = x2 + ((b*CC + ch)*HWSZ) + ghc*WW + gwc;
                tof[k]  = ch*CH_WORDS + X1_WORDS + swz(row*X2_COLS + 4*v);
                tsz[k]  = ok ? 16 : 0;
            }
        } else {
            tsrc[k] = x1;
            tof[k]  = 0;
            tsz[k]  = -1;
        }
    }

    const uint32_t sb0 = smem_u32(&smem[0]);
    const uint32_t sb1 = smem_u32(&smem[STAGE_WORDS]);

    // ---- compute offsets (all swizzled, hoisted) ----
    const int rr   = hl + 8 - wid;                 // main halo row
    const int s1b  = hl*WT + 8*g;
    const int s2b  = rr*X2_COLS + 8*g;
    const int sw1a = swz(s1b),     sw1b = swz(s1b + 4);
    const int sw2a = swz(s2b),     sw2b = swz(s2b + 4);
    const int sw2c = swz(s2b + 8), sw2d = swz(s2b + 12);
    const int s3   = hl2*WT + 2*lane;
    const int s4   = hl2*X2_COLS + 2*lane + (tj ? 0 : 4);
    const int sw3  = swz(s3);
    const int sw4a = swz(s4), sw4b = swz(s4 + 2), sw4c = swz(s4 + 4);

    float acc[9][8];
    #pragma unroll
    for (int j = 0; j < 9; ++j)
        #pragma unroll
        for (int p = 0; p < 8; ++p) acc[j][p] = 0.0f;
    float acc8[5][2];
    #pragma unroll
    for (int jj = 0; jj < 5; ++jj) acc8[jj][0] = acc8[jj][1] = 0.0f;

    // ---- prologue ----
    #pragma unroll
    for (int k = 0; k < NSLOT; ++k)
        if (tsz[k] >= 0) cp_async16(sb0 + (uint32_t)tof[k]*4u, tsrc[k], tsz[k]);
    cp_commit();
    cp_wait_all();
    __syncthreads();

    // ---- main loop: prefetch s+1 while computing s ----
    for (int s = 0; s < NSTAGE; ++s) {
        const int buf = s & 1;
        if (s + 1 < NSTAGE) {
            const uint32_t sbn = (buf ? sb0 : sb1);
            const int adv = (s + 1) * NC * HWSZ;
            #pragma unroll
            for (int k = 0; k < NSLOT; ++k)
                if (tsz[k] >= 0) cp_async16(sbn + (uint32_t)tof[k]*4u, tsrc[k] + adv, tsz[k]);
            cp_commit();
        }

        const float* sbuf = smem + buf*STAGE_WORDS;
        if (tj) do_stage<1>(sbuf, sw1a, sw1b, sw2a, sw2b, sw2c, sw2d,
                            sw3, sw4a, sw4b, sw4c, acc, acc8);
        else    do_stage<0>(sbuf, sw1a, sw1b, sw2a, sw2b, sw2c, sw2d,
                            sw3, sw4a, sw4b, sw4c, acc, acc8);

        cp_wait_all();
        __syncthreads();
    }

    // ---- epilogue ----
    const float inv = 1.0f / 81.0f;

    {
        const int h = h0 + hl;
        float* obase = out + (b*81)*HWSZ + h*WW + w0 + 8*g;
        #pragma unroll
        for (int j = 0; j < 9; ++j) {
            int idx = 9*wid + j + 41;
            if (idx >= 81) idx -= 81;
            float* op = obase + idx*HWSZ;
            *(float4*)(op)   = make_float4(acc[j][0]*inv, acc[j][1]*inv,
                                           acc[j][2]*inv, acc[j][3]*inv);
            *(float4*)(op+4) = make_float4(acc[j][4]*inv, acc[j][5]*inv,
                                           acc[j][6]*inv, acc[j][7]*inv);
        }
    }

    {
        const int h = h0 + hl2;
        float* obase = out + (b*81)*HWSZ + h*WW + w0 + 2*lane;
        if (tj) {
            #pragma unroll
            for (int jj = 0; jj < 4; ++jj) {
                int idx = 32 + 5 + jj;
                *(float2*)(obase + idx*HWSZ) =
                    make_float2(acc8[jj][0]*inv, acc8[jj][1]*inv);
            }
        } else {
            #pragma unroll
            for (int jj = 0; jj < 5; ++jj) {
                int idx = 32 + jj;
                *(float2*)(obase + idx*HWSZ) =
                    make_float2(acc8[jj][0]*inv, acc8[jj][1]*inv);
            }
        }
    }
}

extern "C" void kernel_launch(void* const* d_in, const int* in_sizes, int n_in,
                              void* d_out, int out_size) {
    const float* x1 = (const float*)d_in[0];
    const float* x2 = (const float*)d_in[1];
    float* out = (float*)d_out;
    cudaFuncSetAttribute(costvol_kernel,
                         cudaFuncAttributeMaxDynamicSharedMemorySize, SMEM_BYTES);
    dim3 grid(WW/WT, HH/HT, BB);   // (4, 32, 8)
    dim3 block(THREADS);
    costvol_kernel<<<grid, block, SMEM_BYTES>>>(x1, x2, out);
}